// round 5
// baseline (speedup 1.0000x reference)
#include <cuda_runtime.h>
#include <cstdint>

#define IN_F 4096
#define OUT_F 4096
#define LORA_R 64
#define SCALING 0.25f
#define M_TOTAL (4 * 2048)

// 64 MB scratch for W_eff = s*Wq + 0.25*(B@A). __device__ global = legal scratch.
__device__ float g_weff[(size_t)OUT_F * IN_F];
__device__ int   g_wq_is_i32;   // 1 if weight_quantized stored as int32, 0 if int8

// ---------------------------------------------------------------------------
// Kernel 0: detect weight storage dtype. If the first 4096 int32 words are all
// in [-8, 7], the buffer is int32-widened int8 (harness dtype list has no
// int8). A genuinely int8-packed buffer read as int32 has ~0 probability of
// passing this test (needs 3 high bytes == sign fill for all 4096 words).
// ---------------------------------------------------------------------------
__global__ void detect_wq_dtype_kernel(const void* __restrict__ wq)
{
    if (threadIdx.x == 0 && blockIdx.x == 0) {
        const int* p = (const int*)wq;
        int ok = 1;
        for (int i = 0; i < 4096; ++i) {
            int v = p[i];
            if (v < -8 || v > 7) { ok = 0; break; }
        }
        g_wq_is_i32 = ok;
    }
}

// ---------------------------------------------------------------------------
// Kernel 1: W_eff[o][i] = ws * Wq[o][i] + SCALING * sum_r B[o][r]*A[r][i]
// ---------------------------------------------------------------------------
__global__ __launch_bounds__(256) void build_weff_kernel(
    const void* __restrict__ wqv, const float* __restrict__ ws,
    const float* __restrict__ A, const float* __restrict__ B)
{
    const int i  = blockIdx.x * 256 + threadIdx.x;
    const int o0 = blockIdx.y * 16;

    __shared__ float Bs[16][LORA_R];
    __shared__ float As[16][256];

    for (int t = threadIdx.x; t < 16 * LORA_R; t += 256) {
        int oo = t / LORA_R, r = t % LORA_R;
        Bs[oo][r] = B[(size_t)(o0 + oo) * LORA_R + r];
    }

    float acc[16];
#pragma unroll
    for (int oo = 0; oo < 16; ++oo) acc[oo] = 0.f;

    for (int rc = 0; rc < LORA_R; rc += 16) {
        __syncthreads();
#pragma unroll
        for (int rr = 0; rr < 16; ++rr)
            As[rr][threadIdx.x] = A[(size_t)(rc + rr) * IN_F + i];
        __syncthreads();
#pragma unroll
        for (int rr = 0; rr < 16; ++rr) {
            float a = As[rr][threadIdx.x];
#pragma unroll
            for (int oo = 0; oo < 16; ++oo)
                acc[oo] = fmaf(a, Bs[oo][rc + rr], acc[oo]);
        }
    }

    const float s      = ws[0];
    const int   is_i32 = g_wq_is_i32;
    const int*     wq32 = (const int*)wqv;
    const int8_t*  wq8  = (const int8_t*)wqv;

#pragma unroll
    for (int oo = 0; oo < 16; ++oo) {
        size_t idx = (size_t)(o0 + oo) * IN_F + i;
        float q = is_i32 ? (float)wq32[idx] : (float)wq8[idx];
        g_weff[idx] = s * q + SCALING * acc[oo];
    }
}

// ---------------------------------------------------------------------------
// Kernel 2: O[m][o] = sum_k X[m][k] * W_eff[o][k]
// Classic SGEMM: BM=BN=128, BK=8, 256 threads, 8x8 per-thread tile.
// ---------------------------------------------------------------------------
#define BM 128
#define BN 128
#define BK 8

__global__ __launch_bounds__(256) void qlora_gemm_kernel(
    const float* __restrict__ X, float* __restrict__ O)
{
    __shared__ __align__(16) float As[BK][BM];   // k-major
    __shared__ __align__(16) float Bs[BK][BN];

    const int tid = threadIdx.x;
    const int bm  = blockIdx.y;
    const int bn  = blockIdx.x;

    const int loadRow = tid >> 1;        // 0..127
    const int loadCol = (tid & 1) * 4;   // 0 or 4

    const float* Xp = X      + (size_t)(bm * BM + loadRow) * IN_F + loadCol;
    const float* Wp = g_weff + (size_t)(bn * BN + loadRow) * IN_F + loadCol;

    const int tr = tid >> 4;   // m-sub 0..15
    const int tc = tid & 15;   // o-sub 0..15

    float acc[8][8];
#pragma unroll
    for (int i = 0; i < 8; ++i)
#pragma unroll
        for (int j = 0; j < 8; ++j) acc[i][j] = 0.f;

    for (int kt = 0; kt < IN_F; kt += BK) {
        float4 xa = *reinterpret_cast<const float4*>(Xp);
        float4 wb = *reinterpret_cast<const float4*>(Wp);

        __syncthreads();
        As[loadCol + 0][loadRow] = xa.x;
        As[loadCol + 1][loadRow] = xa.y;
        As[loadCol + 2][loadRow] = xa.z;
        As[loadCol + 3][loadRow] = xa.w;
        Bs[loadCol + 0][loadRow] = wb.x;
        Bs[loadCol + 1][loadRow] = wb.y;
        Bs[loadCol + 2][loadRow] = wb.z;
        Bs[loadCol + 3][loadRow] = wb.w;
        __syncthreads();

#pragma unroll
        for (int k = 0; k < BK; ++k) {
            float4 a0 = *reinterpret_cast<const float4*>(&As[k][tr * 8]);
            float4 a1 = *reinterpret_cast<const float4*>(&As[k][tr * 8 + 4]);
            float4 b0 = *reinterpret_cast<const float4*>(&Bs[k][tc * 8]);
            float4 b1 = *reinterpret_cast<const float4*>(&Bs[k][tc * 8 + 4]);

            float ar[8] = {a0.x, a0.y, a0.z, a0.w, a1.x, a1.y, a1.z, a1.w};
            float br[8] = {b0.x, b0.y, b0.z, b0.w, b1.x, b1.y, b1.z, b1.w};
#pragma unroll
            for (int im = 0; im < 8; ++im)
#pragma unroll
                for (int jn = 0; jn < 8; ++jn)
                    acc[im][jn] = fmaf(ar[im], br[jn], acc[im][jn]);
        }

        Xp += BK;
        Wp += BK;
    }

#pragma unroll
    for (int im = 0; im < 8; ++im) {
        float* Op = O + (size_t)(bm * BM + tr * 8 + im) * OUT_F + bn * BN + tc * 8;
        float4 q0 = make_float4(acc[im][0], acc[im][1], acc[im][2], acc[im][3]);
        float4 q1 = make_float4(acc[im][4], acc[im][5], acc[im][6], acc[im][7]);
        *reinterpret_cast<float4*>(Op)     = q0;
        *reinterpret_cast<float4*>(Op + 4) = q1;
    }
}

// ---------------------------------------------------------------------------
// Launch. Inputs identified BY ELEMENT COUNT (robust to ordering):
//   x      : 33,554,432   fp32
//   wq     : 16,777,216   int32 (widened int8) or int8 — detected on device
//   ws     : 1            fp32
//   lora_A : 262,144      fp32  (first of the two 262,144 entries; A precedes
//   lora_B : 262,144      fp32   B in both dict and alphabetical order)
// ---------------------------------------------------------------------------
extern "C" void kernel_launch(void* const* d_in, const int* in_sizes, int n_in,
                              void* d_out, int out_size)
{
    const float* x  = nullptr;
    const void*  wq = nullptr;
    const float* ws = nullptr;
    const float* la = nullptr;
    const float* lb = nullptr;

    int lora_seen = 0;
    for (int i = 0; i < n_in; ++i) {
        long n = (long)in_sizes[i];
        if (n == 33554432L)        x  = (const float*)d_in[i];
        else if (n == 16777216L)   wq = d_in[i];
        else if (n == 1L)          ws = (const float*)d_in[i];
        else if (n == 262144L) {
            if (lora_seen++ == 0) la = (const float*)d_in[i];
            else                  lb = (const float*)d_in[i];
        }
    }

    float* out = (float*)d_out;

    detect_wq_dtype_kernel<<<1, 1>>>(wq);
    build_weff_kernel<<<dim3(IN_F / 256, OUT_F / 16), 256>>>(wq, ws, la, lb);
    qlora_gemm_kernel<<<dim3(OUT_F / BN, M_TOTAL / BM), 256>>>(x, out);
}

// round 8
// speedup vs baseline: 2.7127x; 2.7127x over previous
#include <cuda_runtime.h>
#include <cuda_bf16.h>
#include <cstdint>

#define IN_F   4096
#define OUT_F  4096
#define LORA_R 64
#define M_TOTAL 8192

// ---------------- device scratch (__device__ globals = legal) ----------------
__device__ __nv_bfloat16 g_xh[(size_t)M_TOTAL * IN_F];   // hi(s*x)   64 MB
__device__ __nv_bfloat16 g_xl[(size_t)M_TOTAL * IN_F];   // lo(s*x)   64 MB
__device__ __nv_bfloat16 g_qbf[(size_t)OUT_F * IN_F];    // Wq as bf16 (exact) 32 MB
__device__ __nv_bfloat16 g_bbf[(size_t)OUT_F * LORA_R];  // lora_B bf16
__device__ __nv_bfloat16 g_t[(size_t)M_TOTAL * LORA_R];  // 0.25 * x @ A^T, bf16
__device__ int g_wq_is_i32;

__device__ __forceinline__ uint32_t smem_u32(const void* p) {
    uint32_t a;
    asm("{ .reg .u64 t; cvta.to.shared.u64 t, %1; cvt.u32.u64 %0, t; }" : "=r"(a) : "l"(p));
    return a;
}

// ---------------- kernel 0: dtype detect ----------------
__global__ void detect_wq_dtype_kernel(const int* __restrict__ wq) {
    __shared__ int bad;
    if (threadIdx.x == 0) bad = 0;
    __syncthreads();
    int v = wq[threadIdx.x * 257];
    if (v < -8 || v > 7) bad = 1;
    __syncthreads();
    if (threadIdx.x == 0) g_wq_is_i32 = !bad;
}

// ---------------- kernel 1: split s*x into bf16 hi/lo ----------------
__global__ __launch_bounds__(256) void split_x_kernel(
    const float* __restrict__ x, const float* __restrict__ ws)
{
    const float s = ws[0];
    size_t i = (size_t)blockIdx.x * 256 + threadIdx.x;   // float4 index
    float4 v = reinterpret_cast<const float4*>(x)[i];
    v.x *= s; v.y *= s; v.z *= s; v.w *= s;
    __nv_bfloat16 h0 = __float2bfloat16(v.x), h1 = __float2bfloat16(v.y);
    __nv_bfloat16 h2 = __float2bfloat16(v.z), h3 = __float2bfloat16(v.w);
    __nv_bfloat16 l0 = __float2bfloat16(v.x - __bfloat162float(h0));
    __nv_bfloat16 l1 = __float2bfloat16(v.y - __bfloat162float(h1));
    __nv_bfloat16 l2 = __float2bfloat16(v.z - __bfloat162float(h2));
    __nv_bfloat16 l3 = __float2bfloat16(v.w - __bfloat162float(h3));
    __nv_bfloat162* ph = reinterpret_cast<__nv_bfloat162*>(g_xh) + i * 2;
    __nv_bfloat162* pl = reinterpret_cast<__nv_bfloat162*>(g_xl) + i * 2;
    ph[0] = __nv_bfloat162(h0, h1); ph[1] = __nv_bfloat162(h2, h3);
    pl[0] = __nv_bfloat162(l0, l1); pl[1] = __nv_bfloat162(l2, l3);
}

// ---------------- kernel 2: Wq -> bf16 (exact for [-8,7]) ----------------
__global__ __launch_bounds__(256) void build_qbf_kernel(const void* __restrict__ wqv) {
    size_t i = ((size_t)blockIdx.x * 256 + threadIdx.x) * 4;
    if (g_wq_is_i32) {
        int4 q = *reinterpret_cast<const int4*>((const int*)wqv + i);
        g_qbf[i + 0] = __float2bfloat16((float)q.x);
        g_qbf[i + 1] = __float2bfloat16((float)q.y);
        g_qbf[i + 2] = __float2bfloat16((float)q.z);
        g_qbf[i + 3] = __float2bfloat16((float)q.w);
    } else {
        const int8_t* p = (const int8_t*)wqv + i;
        g_qbf[i + 0] = __float2bfloat16((float)p[0]);
        g_qbf[i + 1] = __float2bfloat16((float)p[1]);
        g_qbf[i + 2] = __float2bfloat16((float)p[2]);
        g_qbf[i + 3] = __float2bfloat16((float)p[3]);
    }
}

// ---------------- kernel 3: lora_B -> bf16 ----------------
__global__ __launch_bounds__(256) void build_bbf_kernel(const float* __restrict__ B) {
    size_t i = ((size_t)blockIdx.x * 256 + threadIdx.x) * 4;
    float4 v = *reinterpret_cast<const float4*>(B + i);
    g_bbf[i + 0] = __float2bfloat16(v.x);
    g_bbf[i + 1] = __float2bfloat16(v.y);
    g_bbf[i + 2] = __float2bfloat16(v.z);
    g_bbf[i + 3] = __float2bfloat16(v.w);
}

// ---------------- kernel 4: t = 0.25 * x @ A^T  (fp32 SIMT, small) ----------------
// grid: M/64 blocks, 256 threads. Each thread: 4(m) x 4(r).
__global__ __launch_bounds__(256) void t_kernel(
    const float* __restrict__ x, const float* __restrict__ A)
{
    __shared__ float xs[64][33];
    __shared__ float as[64][33];
    const int tid = threadIdx.x;
    const int bm = blockIdx.x;
    const int tr = tid >> 4, tc = tid & 15;

    float acc[4][4];
#pragma unroll
    for (int i = 0; i < 4; ++i)
#pragma unroll
        for (int j = 0; j < 4; ++j) acc[i][j] = 0.f;

    for (int k0 = 0; k0 < IN_F; k0 += 32) {
#pragma unroll
        for (int u = 0; u < 2; ++u) {
            int idx = tid + u * 256;           // 512 float4 chunks
            int row = idx >> 3, c = idx & 7;
            float4 xv = *reinterpret_cast<const float4*>(
                x + (size_t)(bm * 64 + row) * IN_F + k0 + c * 4);
            float4 av = *reinterpret_cast<const float4*>(
                A + (size_t)row * IN_F + k0 + c * 4);
            xs[row][c * 4 + 0] = xv.x; xs[row][c * 4 + 1] = xv.y;
            xs[row][c * 4 + 2] = xv.z; xs[row][c * 4 + 3] = xv.w;
            as[row][c * 4 + 0] = av.x; as[row][c * 4 + 1] = av.y;
            as[row][c * 4 + 2] = av.z; as[row][c * 4 + 3] = av.w;
        }
        __syncthreads();
#pragma unroll
        for (int kk = 0; kk < 32; ++kk) {
            float xv[4], av[4];
#pragma unroll
            for (int i = 0; i < 4; ++i) xv[i] = xs[tr * 4 + i][kk];
#pragma unroll
            for (int j = 0; j < 4; ++j) av[j] = as[tc * 4 + j][kk];
#pragma unroll
            for (int i = 0; i < 4; ++i)
#pragma unroll
                for (int j = 0; j < 4; ++j)
                    acc[i][j] = fmaf(xv[i], av[j], acc[i][j]);
        }
        __syncthreads();
    }
#pragma unroll
    for (int i = 0; i < 4; ++i)
#pragma unroll
        for (int j = 0; j < 4; ++j)
            g_t[(size_t)(bm * 64 + tr * 4 + i) * LORA_R + tc * 4 + j] =
                __float2bfloat16(0.25f * acc[i][j]);
}

// ---------------- kernel 5: main mma.sync GEMM ----------------
// out[m][n] = xh@q + xl@q + t@bbf (all K-concatenated). K' = 8256.
// BM=BN=128, BK=32, 8 warps (2 m x 4 n), warp tile 64x32, m16n8k16 bf16.
#define SSTR 40                  // smem row stride in bf16 (conflict-free ldmatrix)
#define NTILES (2 * (IN_F / 32) + 2)   // 128 + 128 + 2 = 258

__device__ __forceinline__ void cp16(uint32_t dst, const void* src) {
    asm volatile("cp.async.cg.shared.global [%0], [%1], 16;" :: "r"(dst), "l"(src) : "memory");
}
__device__ __forceinline__ void ldmx4(uint32_t addr, uint32_t& r0, uint32_t& r1,
                                      uint32_t& r2, uint32_t& r3) {
    asm volatile("ldmatrix.sync.aligned.m8n8.x4.shared.b16 {%0,%1,%2,%3}, [%4];"
                 : "=r"(r0), "=r"(r1), "=r"(r2), "=r"(r3) : "r"(addr));
}
__device__ __forceinline__ void mma16816(float* c, const uint32_t* a, const uint32_t* b) {
    asm volatile(
        "mma.sync.aligned.m16n8k16.row.col.f32.bf16.bf16.f32 "
        "{%0,%1,%2,%3}, {%4,%5,%6,%7}, {%8,%9}, {%0,%1,%2,%3};"
        : "+f"(c[0]), "+f"(c[1]), "+f"(c[2]), "+f"(c[3])
        : "r"(a[0]), "r"(a[1]), "r"(a[2]), "r"(a[3]), "r"(b[0]), "r"(b[1]));
}

__global__ __launch_bounds__(256) void qlora_mma_kernel(float* __restrict__ out)
{
    __shared__ __align__(16) __nv_bfloat16 sA[2][128 * SSTR];
    __shared__ __align__(16) __nv_bfloat16 sW[2][128 * SSTR];

    const int tid  = threadIdx.x;
    const int wid  = tid >> 5;
    const int lane = tid & 31;
    const int warp_m = wid & 1;      // 0..1
    const int warp_n = wid >> 1;     // 0..3
    const int bm = blockIdx.y, bn = blockIdx.x;

    float acc[4][4][4];
#pragma unroll
    for (int i = 0; i < 4; ++i)
#pragma unroll
        for (int j = 0; j < 4; ++j)
#pragma unroll
            for (int r = 0; r < 4; ++r) acc[i][j][r] = 0.f;

    // per-thread staging chunks: A has 512 16B chunks (128 rows x 4), same W
    const int ch0 = tid, ch1 = tid + 256;

    // issue cp.async for tile kt into stage s
    auto issue = [&](int kt, int s) {
        const __nv_bfloat16 *aSrc, *wSrc;
        int lda, ko;
        if (kt < 128)      { aSrc = g_xh; wSrc = g_qbf; lda = IN_F;   ko = kt * 32; }
        else if (kt < 256) { aSrc = g_xl; wSrc = g_qbf; lda = IN_F;   ko = (kt - 128) * 32; }
        else               { aSrc = g_t;  wSrc = g_bbf; lda = LORA_R; ko = (kt - 256) * 32; }
        const __nv_bfloat16* aBase = aSrc + (size_t)(bm * 128) * lda + ko;
        const __nv_bfloat16* wBase = wSrc + (size_t)(bn * 128) * lda + ko;
        uint32_t dA = smem_u32(&sA[s][0]);
        uint32_t dW = smem_u32(&sW[s][0]);
#pragma unroll
        for (int u = 0; u < 2; ++u) {
            int c = u ? ch1 : ch0;
            int row = c >> 2, kc = (c & 3) * 8;
            cp16(dA + (uint32_t)(row * SSTR + kc) * 2, aBase + (size_t)row * lda + kc);
            cp16(dW + (uint32_t)(row * SSTR + kc) * 2, wBase + (size_t)row * lda + kc);
        }
        asm volatile("cp.async.commit_group;" ::: "memory");
    };

    issue(0, 0);

    const int rowA = warp_m * 64 + (lane & 15);
    const int rowW = warp_n * 32 + (lane & 7) + ((lane >> 3) & 1) * 8;
    const int koff = (lane >> 4) * 8;

    for (int kt = 0; kt < NTILES; ++kt) {
        const int s = kt & 1;
        if (kt + 1 < NTILES) {
            issue(kt + 1, s ^ 1);
            asm volatile("cp.async.wait_group 1;" ::: "memory");
        } else {
            asm volatile("cp.async.wait_group 0;" ::: "memory");
        }
        __syncthreads();

        const uint32_t bA = smem_u32(&sA[s][0]);
        const uint32_t bW = smem_u32(&sW[s][0]);
#pragma unroll
        for (int ks = 0; ks < 2; ++ks) {
            const int kb = ks * 16 + koff;
            uint32_t af[4][4], bf[4][2];
#pragma unroll
            for (int mf = 0; mf < 4; ++mf)
                ldmx4(bA + (uint32_t)((rowA + mf * 16) * SSTR + kb) * 2,
                      af[mf][0], af[mf][1], af[mf][2], af[mf][3]);
#pragma unroll
            for (int nf2 = 0; nf2 < 2; ++nf2) {
                uint32_t r0, r1, r2, r3;
                ldmx4(bW + (uint32_t)((rowW + nf2 * 16) * SSTR + kb) * 2, r0, r1, r2, r3);
                bf[nf2 * 2 + 0][0] = r0; bf[nf2 * 2 + 0][1] = r2;
                bf[nf2 * 2 + 1][0] = r1; bf[nf2 * 2 + 1][1] = r3;
            }
#pragma unroll
            for (int mf = 0; mf < 4; ++mf)
#pragma unroll
                for (int nf = 0; nf < 4; ++nf)
                    mma16816(acc[mf][nf], af[mf], bf[nf]);
        }
        __syncthreads();
    }

    // epilogue: frag (g=lane>>2 row, 2t cols), rows +8 for c2/c3
    const int g = lane >> 2, t4 = lane & 3;
#pragma unroll
    for (int mf = 0; mf < 4; ++mf) {
#pragma unroll
        for (int nf = 0; nf < 4; ++nf) {
            int m = bm * 128 + warp_m * 64 + mf * 16 + g;
            int n = bn * 128 + warp_n * 32 + nf * 8 + t4 * 2;
            float2* p0 = reinterpret_cast<float2*>(out + (size_t)m * OUT_F + n);
            float2* p1 = reinterpret_cast<float2*>(out + (size_t)(m + 8) * OUT_F + n);
            *p0 = make_float2(acc[mf][nf][0], acc[mf][nf][1]);
            *p1 = make_float2(acc[mf][nf][2], acc[mf][nf][3]);
        }
    }
}

// ---------------- launch ----------------
extern "C" void kernel_launch(void* const* d_in, const int* in_sizes, int n_in,
                              void* d_out, int out_size)
{
    const float* x  = nullptr;
    const void*  wq = nullptr;
    const float* ws = nullptr;
    const float* la = nullptr;
    const float* lb = nullptr;

    int lora_seen = 0;
    for (int i = 0; i < n_in; ++i) {
        long n = (long)in_sizes[i];
        if (n == 33554432L)      x  = (const float*)d_in[i];
        else if (n == 16777216L) wq = d_in[i];
        else if (n == 1L)        ws = (const float*)d_in[i];
        else if (n == 262144L) {
            if (lora_seen++ == 0) la = (const float*)d_in[i];
            else                  lb = (const float*)d_in[i];
        }
    }
    float* out = (float*)d_out;

    detect_wq_dtype_kernel<<<1, 256>>>((const int*)wq);
    split_x_kernel<<<(M_TOTAL * IN_F / 4) / 256, 256>>>(x, ws);
    build_qbf_kernel<<<(OUT_F * IN_F / 4) / 256, 256>>>(wq);
    build_bbf_kernel<<<(OUT_F * LORA_R / 4) / 256, 256>>>(lb);
    t_kernel<<<M_TOTAL / 64, 256>>>(x, la);
    qlora_mma_kernel<<<dim3(OUT_F / 128, M_TOTAL / 128), 256>>>(out);
}

// round 9
// speedup vs baseline: 2.8514x; 1.0511x over previous
#include <cuda_runtime.h>
#include <cuda_bf16.h>
#include <cstdint>

#define IN_F   4096
#define OUT_F  4096
#define LORA_R 64
#define M_TOTAL 8192

// ---------------- device scratch ----------------
__device__ __nv_bfloat16 g_xh[(size_t)M_TOTAL * IN_F];
__device__ __nv_bfloat16 g_xl[(size_t)M_TOTAL * IN_F];
__device__ __nv_bfloat16 g_qbf[(size_t)OUT_F * IN_F];
__device__ __nv_bfloat16 g_bbf[(size_t)OUT_F * LORA_R];
__device__ __nv_bfloat16 g_t[(size_t)M_TOTAL * LORA_R];
__device__ int g_wq_is_i32;

__device__ __forceinline__ uint32_t smem_u32(const void* p) {
    uint32_t a;
    asm("{ .reg .u64 t; cvta.to.shared.u64 t, %1; cvt.u32.u64 %0, t; }" : "=r"(a) : "l"(p));
    return a;
}

// ---------------- kernel 0: dtype detect ----------------
__global__ void detect_wq_dtype_kernel(const int* __restrict__ wq) {
    __shared__ int bad;
    if (threadIdx.x == 0) bad = 0;
    __syncthreads();
    int v = wq[threadIdx.x * 257];
    if (v < -8 || v > 7) bad = 1;
    __syncthreads();
    if (threadIdx.x == 0) g_wq_is_i32 = !bad;
}

// ---------------- kernel 1: split s*x into bf16 hi/lo ----------------
__global__ __launch_bounds__(256) void split_x_kernel(
    const float* __restrict__ x, const float* __restrict__ ws)
{
    const float s = ws[0];
    size_t i = (size_t)blockIdx.x * 256 + threadIdx.x;
    float4 v = reinterpret_cast<const float4*>(x)[i];
    v.x *= s; v.y *= s; v.z *= s; v.w *= s;
    __nv_bfloat16 h0 = __float2bfloat16(v.x), h1 = __float2bfloat16(v.y);
    __nv_bfloat16 h2 = __float2bfloat16(v.z), h3 = __float2bfloat16(v.w);
    __nv_bfloat16 l0 = __float2bfloat16(v.x - __bfloat162float(h0));
    __nv_bfloat16 l1 = __float2bfloat16(v.y - __bfloat162float(h1));
    __nv_bfloat16 l2 = __float2bfloat16(v.z - __bfloat162float(h2));
    __nv_bfloat16 l3 = __float2bfloat16(v.w - __bfloat162float(h3));
    __nv_bfloat162* ph = reinterpret_cast<__nv_bfloat162*>(g_xh) + i * 2;
    __nv_bfloat162* pl = reinterpret_cast<__nv_bfloat162*>(g_xl) + i * 2;
    ph[0] = __nv_bfloat162(h0, h1); ph[1] = __nv_bfloat162(h2, h3);
    pl[0] = __nv_bfloat162(l0, l1); pl[1] = __nv_bfloat162(l2, l3);
}

// ---------------- kernel 2: Wq -> bf16 (exact) ----------------
__global__ __launch_bounds__(256) void build_qbf_kernel(const void* __restrict__ wqv) {
    size_t i = ((size_t)blockIdx.x * 256 + threadIdx.x) * 4;
    if (g_wq_is_i32) {
        int4 q = *reinterpret_cast<const int4*>((const int*)wqv + i);
        g_qbf[i + 0] = __float2bfloat16((float)q.x);
        g_qbf[i + 1] = __float2bfloat16((float)q.y);
        g_qbf[i + 2] = __float2bfloat16((float)q.z);
        g_qbf[i + 3] = __float2bfloat16((float)q.w);
    } else {
        const int8_t* p = (const int8_t*)wqv + i;
        g_qbf[i + 0] = __float2bfloat16((float)p[0]);
        g_qbf[i + 1] = __float2bfloat16((float)p[1]);
        g_qbf[i + 2] = __float2bfloat16((float)p[2]);
        g_qbf[i + 3] = __float2bfloat16((float)p[3]);
    }
}

// ---------------- kernel 3: lora_B -> bf16 ----------------
__global__ __launch_bounds__(256) void build_bbf_kernel(const float* __restrict__ B) {
    size_t i = ((size_t)blockIdx.x * 256 + threadIdx.x) * 4;
    float4 v = *reinterpret_cast<const float4*>(B + i);
    g_bbf[i + 0] = __float2bfloat16(v.x);
    g_bbf[i + 1] = __float2bfloat16(v.y);
    g_bbf[i + 2] = __float2bfloat16(v.z);
    g_bbf[i + 3] = __float2bfloat16(v.w);
}

// ---------------- kernel 4: t = 0.25 * x @ A^T ----------------
__global__ __launch_bounds__(256) void t_kernel(
    const float* __restrict__ x, const float* __restrict__ A)
{
    __shared__ float xs[64][33];
    __shared__ float as[64][33];
    const int tid = threadIdx.x;
    const int bm = blockIdx.x;
    const int tr = tid >> 4, tc = tid & 15;

    float acc[4][4];
#pragma unroll
    for (int i = 0; i < 4; ++i)
#pragma unroll
        for (int j = 0; j < 4; ++j) acc[i][j] = 0.f;

    for (int k0 = 0; k0 < IN_F; k0 += 32) {
#pragma unroll
        for (int u = 0; u < 2; ++u) {
            int idx = tid + u * 256;
            int row = idx >> 3, c = idx & 7;
            float4 xv = *reinterpret_cast<const float4*>(
                x + (size_t)(bm * 64 + row) * IN_F + k0 + c * 4);
            float4 av = *reinterpret_cast<const float4*>(
                A + (size_t)row * IN_F + k0 + c * 4);
            xs[row][c * 4 + 0] = xv.x; xs[row][c * 4 + 1] = xv.y;
            xs[row][c * 4 + 2] = xv.z; xs[row][c * 4 + 3] = xv.w;
            as[row][c * 4 + 0] = av.x; as[row][c * 4 + 1] = av.y;
            as[row][c * 4 + 2] = av.z; as[row][c * 4 + 3] = av.w;
        }
        __syncthreads();
#pragma unroll
        for (int kk = 0; kk < 32; ++kk) {
            float xv[4], av[4];
#pragma unroll
            for (int i = 0; i < 4; ++i) xv[i] = xs[tr * 4 + i][kk];
#pragma unroll
            for (int j = 0; j < 4; ++j) av[j] = as[tc * 4 + j][kk];
#pragma unroll
            for (int i = 0; i < 4; ++i)
#pragma unroll
                for (int j = 0; j < 4; ++j)
                    acc[i][j] = fmaf(xv[i], av[j], acc[i][j]);
        }
        __syncthreads();
    }
#pragma unroll
    for (int i = 0; i < 4; ++i)
#pragma unroll
        for (int j = 0; j < 4; ++j)
            g_t[(size_t)(bm * 64 + tr * 4 + i) * LORA_R + tc * 4 + j] =
                __float2bfloat16(0.25f * acc[i][j]);
}

// ---------------- kernel 5: main mma.sync GEMM ----------------
// CTA 256(M) x 128(N), BK=32, 8 warps (4m x 2n), warp tile 64x64.
// 4-stage cp.async ring, K' = 4096(hi) + 4096(lo) + 64(lora) -> 258 tiles.
#define SSTR 40
#define NTILES (2 * (IN_F / 32) + 2)
#define A_ROWS 256
#define W_ROWS 128
#define STAGE_BF16 ((A_ROWS + W_ROWS) * SSTR)       // 15360 bf16
#define STAGES 4
#define SMEM_MAIN (STAGES * STAGE_BF16 * 2)          // 122880 B

__device__ __forceinline__ void cp16(uint32_t dst, const void* src) {
    asm volatile("cp.async.cg.shared.global [%0], [%1], 16;" :: "r"(dst), "l"(src) : "memory");
}
__device__ __forceinline__ void ldmx4(uint32_t addr, uint32_t& r0, uint32_t& r1,
                                      uint32_t& r2, uint32_t& r3) {
    asm volatile("ldmatrix.sync.aligned.m8n8.x4.shared.b16 {%0,%1,%2,%3}, [%4];"
                 : "=r"(r0), "=r"(r1), "=r"(r2), "=r"(r3) : "r"(addr));
}
__device__ __forceinline__ void mma16816(float* c, const uint32_t* a, const uint32_t* b) {
    asm volatile(
        "mma.sync.aligned.m16n8k16.row.col.f32.bf16.bf16.f32 "
        "{%0,%1,%2,%3}, {%4,%5,%6,%7}, {%8,%9}, {%0,%1,%2,%3};"
        : "+f"(c[0]), "+f"(c[1]), "+f"(c[2]), "+f"(c[3])
        : "r"(a[0]), "r"(a[1]), "r"(a[2]), "r"(a[3]), "r"(b[0]), "r"(b[1]));
}

__global__ __launch_bounds__(256, 1) void qlora_mma_kernel(float* __restrict__ out)
{
    extern __shared__ __align__(16) __nv_bfloat16 smem[];

    const int tid  = threadIdx.x;
    const int wid  = tid >> 5;
    const int lane = tid & 31;
    const int warp_m = wid & 3;      // 0..3
    const int warp_n = wid >> 2;     // 0..1
    const int bm = blockIdx.y, bn = blockIdx.x;
    const uint32_t sbase = smem_u32(smem);

    float acc[4][8][4];
#pragma unroll
    for (int i = 0; i < 4; ++i)
#pragma unroll
        for (int j = 0; j < 8; ++j)
#pragma unroll
            for (int r = 0; r < 4; ++r) acc[i][j][r] = 0.f;

    // issue cp.async for tile kt into ring stage; empty commit past the end
    auto issue = [&](int kt) {
        if (kt < NTILES) {
            const int s = kt & (STAGES - 1);
            const __nv_bfloat16 *aSrc, *wSrc;
            int lda, ko;
            if (kt < 128)      { aSrc = g_xh; wSrc = g_qbf; lda = IN_F;   ko = kt * 32; }
            else if (kt < 256) { aSrc = g_xl; wSrc = g_qbf; lda = IN_F;   ko = (kt - 128) * 32; }
            else               { aSrc = g_t;  wSrc = g_bbf; lda = LORA_R; ko = (kt - 256) * 32; }
            const __nv_bfloat16* aBase = aSrc + (size_t)(bm * A_ROWS) * lda + ko;
            const __nv_bfloat16* wBase = wSrc + (size_t)(bn * W_ROWS) * lda + ko;
            const uint32_t dA = sbase + (uint32_t)(s * STAGE_BF16) * 2;
            const uint32_t dW = dA + (uint32_t)(A_ROWS * SSTR) * 2;
            // A: 256x32 = 1024 16B-chunks -> 4/thread
#pragma unroll
            for (int u = 0; u < 4; ++u) {
                int c = tid + u * 256;
                int row = c >> 2, kc = (c & 3) * 8;
                cp16(dA + (uint32_t)(row * SSTR + kc) * 2, aBase + (size_t)row * lda + kc);
            }
            // W: 128x32 = 512 chunks -> 2/thread
#pragma unroll
            for (int u = 0; u < 2; ++u) {
                int c = tid + u * 256;
                int row = c >> 2, kc = (c & 3) * 8;
                cp16(dW + (uint32_t)(row * SSTR + kc) * 2, wBase + (size_t)row * lda + kc);
            }
        }
        asm volatile("cp.async.commit_group;" ::: "memory");
    };

    issue(0); issue(1); issue(2);

    const int rowA = warp_m * 64 + (lane & 15);
    const int rowW = warp_n * 64 + (lane & 7) + ((lane >> 3) & 1) * 8;
    const int koff = (lane >> 4) * 8;

    for (int kt = 0; kt < NTILES; ++kt) {
        const int s = kt & (STAGES - 1);
        asm volatile("cp.async.wait_group 2;" ::: "memory");
        __syncthreads();          // all warps done with stage (kt-1)%4 == (kt+3)%4
        issue(kt + 3);

        const uint32_t bA = sbase + (uint32_t)(s * STAGE_BF16) * 2;
        const uint32_t bW = bA + (uint32_t)(A_ROWS * SSTR) * 2;
#pragma unroll
        for (int ks = 0; ks < 2; ++ks) {
            const int kb = ks * 16 + koff;
            uint32_t af[4][4], bf[8][2];
#pragma unroll
            for (int mf = 0; mf < 4; ++mf)
                ldmx4(bA + (uint32_t)((rowA + mf * 16) * SSTR + kb) * 2,
                      af[mf][0], af[mf][1], af[mf][2], af[mf][3]);
#pragma unroll
            for (int nf2 = 0; nf2 < 4; ++nf2) {
                uint32_t r0, r1, r2, r3;
                ldmx4(bW + (uint32_t)((rowW + nf2 * 16) * SSTR + kb) * 2, r0, r1, r2, r3);
                bf[nf2 * 2 + 0][0] = r0; bf[nf2 * 2 + 0][1] = r2;
                bf[nf2 * 2 + 1][0] = r1; bf[nf2 * 2 + 1][1] = r3;
            }
#pragma unroll
            for (int mf = 0; mf < 4; ++mf)
#pragma unroll
                for (int nf = 0; nf < 8; ++nf)
                    mma16816(acc[mf][nf], af[mf], bf[nf]);
        }
    }

    // epilogue
    const int g = lane >> 2, t4 = lane & 3;
#pragma unroll
    for (int mf = 0; mf < 4; ++mf) {
#pragma unroll
        for (int nf = 0; nf < 8; ++nf) {
            int m = bm * 256 + warp_m * 64 + mf * 16 + g;
            int n = bn * 128 + warp_n * 64 + nf * 8 + t4 * 2;
            float2* p0 = reinterpret_cast<float2*>(out + (size_t)m * OUT_F + n);
            float2* p1 = reinterpret_cast<float2*>(out + (size_t)(m + 8) * OUT_F + n);
            *p0 = make_float2(acc[mf][nf][0], acc[mf][nf][1]);
            *p1 = make_float2(acc[mf][nf][2], acc[mf][nf][3]);
        }
    }
}

// ---------------- launch ----------------
extern "C" void kernel_launch(void* const* d_in, const int* in_sizes, int n_in,
                              void* d_out, int out_size)
{
    const float* x  = nullptr;
    const void*  wq = nullptr;
    const float* ws = nullptr;
    const float* la = nullptr;
    const float* lb = nullptr;

    int lora_seen = 0;
    for (int i = 0; i < n_in; ++i) {
        long n = (long)in_sizes[i];
        if (n == 33554432L)      x  = (const float*)d_in[i];
        else if (n == 16777216L) wq = d_in[i];
        else if (n == 1L)        ws = (const float*)d_in[i];
        else if (n == 262144L) {
            if (lora_seen++ == 0) la = (const float*)d_in[i];
            else                  lb = (const float*)d_in[i];
        }
    }
    float* out = (float*)d_out;

    cudaFuncSetAttribute(qlora_mma_kernel,
                         cudaFuncAttributeMaxDynamicSharedMemorySize, SMEM_MAIN);

    detect_wq_dtype_kernel<<<1, 256>>>((const int*)wq);
    split_x_kernel<<<(M_TOTAL * IN_F / 4) / 256, 256>>>(x, ws);
    build_qbf_kernel<<<(OUT_F * IN_F / 4) / 256, 256>>>(wq);
    build_bbf_kernel<<<(OUT_F * LORA_R / 4) / 256, 256>>>(lb);
    t_kernel<<<M_TOTAL / 64, 256>>>(x, la);
    qlora_mma_kernel<<<dim3(OUT_F / 128, M_TOTAL / 256), 256, SMEM_MAIN>>>(out);
}